// round 6
// baseline (speedup 1.0000x reference)
#include <cuda_runtime.h>

// ---------------------------------------------------------------------------
// Problem constants
// ---------------------------------------------------------------------------
#define NN      4096
#define IN_DIM  256
#define HID     64
#define NHEADS  4
#define ODIM    128
#define NSLICE  4          // j-split for layer-2 attention

// ---------------------------------------------------------------------------
// Scratch (device globals; no allocation allowed)
// ---------------------------------------------------------------------------
__device__ float g_Wcat[IN_DIM * 256];          // packed per-head W -> [256,256]
__device__ float g_Wh1 [NN * 256];              // layer-1 Wh, heads concat on cols
__device__ float g_f11 [NHEADS * NN];
__device__ float g_f21 [NHEADS * NN];
__device__ float g_h1  [NN * 256];              // layer-1 output (elu'd, concat)
__device__ float g_Wh2 [NN * ODIM];
__device__ float g_f12 [NN];
__device__ float g_f22 [NN];
__device__ float g_num2[NSLICE * NN * ODIM];    // layer-2 partial numerators
__device__ float g_den2[NSLICE * NN];           // layer-2 partial denominators

// ---------------------------------------------------------------------------
// Packed fp32x2 helpers (Blackwell)
// ---------------------------------------------------------------------------
__device__ __forceinline__ unsigned long long pack2(float v) {
    unsigned int u = __float_as_uint(v);
    unsigned long long r;
    asm("mov.b64 %0, {%1, %1};" : "=l"(r) : "r"(u));
    return r;
}
__device__ __forceinline__ void ffma2(unsigned long long &d,
                                      unsigned long long a,
                                      unsigned long long b) {
    asm("fma.rn.f32x2 %0, %1, %2, %0;" : "+l"(d) : "l"(a), "l"(b));
}
__device__ __forceinline__ void unpack2(unsigned long long v, float &lo, float &hi) {
    unsigned int a, b;
    asm("mov.b64 {%0, %1}, %2;" : "=r"(a), "=r"(b) : "l"(v));
    lo = __uint_as_float(a);
    hi = __uint_as_float(b);
}

// ---------------------------------------------------------------------------
// Pack W_heads [4][256][64] -> Wcat [256][256] (col c = head c/64, feat c%64)
// ---------------------------------------------------------------------------
__global__ void packw_kernel(const float* __restrict__ W_heads) {
    int idx = blockIdx.x * 256 + threadIdx.x;      // 65536 total
    int k = idx >> 8, c = idx & 255;
    int h = c >> 6, f = c & 63;
    g_Wcat[idx] = W_heads[(h * 256 + k) * 64 + f];
    (void)k;
}

// ---------------------------------------------------------------------------
// Simple tiled fp32 GEMM: C[M,Nc] = A[M,K] @ B[K,Nc].  64x64 tile, BK=16,
// 256 threads, 4x4 per-thread micro-tile.  M,Nc,K all multiples of tile dims.
// ---------------------------------------------------------------------------
__global__ __launch_bounds__(256)
void gemm_kernel(const float* __restrict__ A, const float* __restrict__ B,
                 float* __restrict__ C, int M, int Nc, int K) {
    __shared__ float As[16][65];   // [k][m] (transposed)
    __shared__ float Bs[16][64];
    int tid = threadIdx.x;
    int row0 = blockIdx.y * 64, col0 = blockIdx.x * 64;
    int tx = tid & 15, ty = tid >> 4;
    int am = tid >> 2, ak = (tid & 3) << 2;
    int bk = tid >> 4, bn = (tid & 15) << 2;
    float acc[4][4] = {};
    for (int k0 = 0; k0 < K; k0 += 16) {
        float4 av = *(const float4*)&A[(size_t)(row0 + am) * K + k0 + ak];
        As[ak + 0][am] = av.x; As[ak + 1][am] = av.y;
        As[ak + 2][am] = av.z; As[ak + 3][am] = av.w;
        *(float4*)&Bs[bk][bn] = *(const float4*)&B[(size_t)(k0 + bk) * Nc + col0 + bn];
        __syncthreads();
#pragma unroll
        for (int k = 0; k < 16; ++k) {
            float a[4];
#pragma unroll
            for (int r = 0; r < 4; ++r) a[r] = As[k][ty * 4 + r];
            float4 bv = *(const float4*)&Bs[k][tx * 4];
            float b[4] = {bv.x, bv.y, bv.z, bv.w};
#pragma unroll
            for (int r = 0; r < 4; ++r)
#pragma unroll
                for (int c = 0; c < 4; ++c)
                    acc[r][c] = fmaf(a[r], b[c], acc[r][c]);
        }
        __syncthreads();
    }
#pragma unroll
    for (int r = 0; r < 4; ++r)
#pragma unroll
        for (int c = 0; c < 4; ++c)
            C[(size_t)(row0 + ty * 4 + r) * Nc + col0 + tx * 4 + c] = acc[r][c];
}

// ---------------------------------------------------------------------------
// f-vectors, layer 1: f1[h][i] = Wh1[i, h*64:h*64+64] . a_heads[h, 0:64]
//                     f2[h][i] = ...                  . a_heads[h,64:128]
// one warp per row i, loops heads.
// ---------------------------------------------------------------------------
__global__ void fk1_kernel(const float* __restrict__ a_heads) {
    int warp = threadIdx.x >> 5, lane = threadIdx.x & 31;
    int i = blockIdx.x * 8 + warp;
#pragma unroll
    for (int h = 0; h < NHEADS; ++h) {
        float w0 = g_Wh1[(size_t)i * 256 + h * 64 + lane];
        float w1 = g_Wh1[(size_t)i * 256 + h * 64 + 32 + lane];
        float p1 = w0 * a_heads[h * 128 + lane]      + w1 * a_heads[h * 128 + 32 + lane];
        float p2 = w0 * a_heads[h * 128 + 64 + lane] + w1 * a_heads[h * 128 + 96 + lane];
#pragma unroll
        for (int o = 16; o; o >>= 1) {
            p1 += __shfl_xor_sync(0xffffffffu, p1, o);
            p2 += __shfl_xor_sync(0xffffffffu, p2, o);
        }
        if (lane == 0) { g_f11[h * NN + i] = p1; g_f21[h * NN + i] = p2; }
    }
}

// f-vectors, layer 2: f1[i] = Wh2[i,:] . a_out[:128];  f2 with a_out[128:]
__global__ void fk2_kernel(const float* __restrict__ a_out) {
    int warp = threadIdx.x >> 5, lane = threadIdx.x & 31;
    int i = blockIdx.x * 8 + warp;
    float s1 = 0.f, s2 = 0.f;
#pragma unroll
    for (int k = 0; k < 4; ++k) {
        float v = g_Wh2[(size_t)i * ODIM + k * 32 + lane];
        s1 = fmaf(v, a_out[k * 32 + lane], s1);
        s2 = fmaf(v, a_out[128 + k * 32 + lane], s2);
    }
#pragma unroll
    for (int o = 16; o; o >>= 1) {
        s1 += __shfl_xor_sync(0xffffffffu, s1, o);
        s2 += __shfl_xor_sync(0xffffffffu, s2, o);
    }
    if (lane == 0) { g_f12[i] = s1; g_f22[i] = s2; }
}

// ---------------------------------------------------------------------------
// Attention aggregation.
//   For rows i0..i0+127 (one block), stream j in tiles of 32:
//     phase A: w_ij = mask ? exp(lrelu(f1[i]+f2[j])) : 0 -> SMEM (pre-packed
//              as (w,w) fp32x2 pairs), per-lane denominator accumulation.
//     phase B: register-tiled MAC  acc[i, c] += w_ij * Wh[j, c]  using
//              fma.rn.f32x2 (2 MAC / lane / inst).
//   FIN=true : normalize + ELU, write directly (layer 1 per-head output).
//   FIN=false: write raw partial numerator + denominator (layer 2 j-split).
// blockIdx.y = head (layer 1) or j-slice (layer 2).
// ---------------------------------------------------------------------------
template<int NF, bool FIN>
__global__ __launch_bounds__(256)
void attn_kernel(const float* __restrict__ Wh, int wh_stride, int wh_col_step,
                 const float* __restrict__ f1b, const float* __restrict__ f2b,
                 int f_step,
                 const int* __restrict__ adj,
                 int j_step_y, int j_len,
                 float* __restrict__ outp, int out_stride, int out_col_step,
                 int out_blk_step,
                 float* __restrict__ den_out, int den_step) {
    constexpr int BM = 128, BN = 32;
    constexpr int Tc = NF / 8;            // threads along feature dim (8 cols each)
    constexpr int R  = BM / (256 / Tc);   // rows per thread (NF=64 -> 4, NF=128 -> 8)
    constexpr int RW = BM / 8;            // rows per warp in phase A (=16)

    extern __shared__ unsigned char smraw[];
    unsigned long long* w_s = (unsigned long long*)smraw;                 // [BM][BN+1]
    float* wh_s  = (float*)(smraw + BM * (BN + 1) * 8);                   // [BN][NF]
    float* den_s = wh_s + BN * NF;                                        // [BM]

    int tid  = threadIdx.x, warp = tid >> 5, lane = tid & 31;
    int y    = blockIdx.y;
    int i0   = blockIdx.x * BM;

    const float* f1 = f1b + y * f_step;
    const float* f2 = f2b + y * f_step;
    int wh_col0 = y * wh_col_step;
    int j_begin = y * j_step_y, j_end = j_begin + j_len;

    float f1r[RW], den_acc[RW];
#pragma unroll
    for (int r = 0; r < RW; ++r) {
        f1r[r] = f1[i0 + warp * RW + r];
        den_acc[r] = 0.f;
    }

    int ct = tid % Tc, rt = tid / Tc;
    int c0 = ct * 8, r0 = rt * R;
    unsigned long long acc[R][4];
#pragma unroll
    for (int r = 0; r < R; ++r)
#pragma unroll
        for (int k = 0; k < 4; ++k) acc[r][k] = 0ull;

    for (int j0 = j_begin; j0 < j_end; j0 += BN) {
        // ---- load Wh tile (coalesced float4) ----
#pragma unroll
        for (int t = 0; t < (BN * NF / 4) / 256; ++t) {
            int idx = t * 256 + tid;
            int jj = idx / (NF / 4), ff = (idx % (NF / 4)) * 4;
            *(float4*)&wh_s[jj * NF + ff] =
                *(const float4*)&Wh[(size_t)(j0 + jj) * wh_stride + wh_col0 + ff];
        }
        // ---- build w tile ----
        float f2v = f2[j0 + lane];
#pragma unroll
        for (int r = 0; r < RW; ++r) {
            int il = warp * RW + r;
            int m  = adj[(size_t)(i0 + il) * NN + j0 + lane];
            float s = f1r[r] + f2v;
            s = fmaxf(s, 0.5f * s);                 // leaky_relu, slope 0.5
            float w = (m != 0) ? __expf(s) : 0.0f;
            w_s[il * (BN + 1) + lane] = pack2(w);
            den_acc[r] += w;
        }
        __syncthreads();
        // ---- MAC phase ----
#pragma unroll 4
        for (int jj = 0; jj < BN; ++jj) {
            ulonglong2 wa = *(const ulonglong2*)&wh_s[jj * NF + c0];
            ulonglong2 wb = *(const ulonglong2*)&wh_s[jj * NF + c0 + 4];
#pragma unroll
            for (int r = 0; r < R; ++r) {
                unsigned long long w2 = w_s[(r0 + r) * (BN + 1) + jj];
                ffma2(acc[r][0], w2, wa.x);
                ffma2(acc[r][1], w2, wa.y);
                ffma2(acc[r][2], w2, wb.x);
                ffma2(acc[r][3], w2, wb.y);
            }
        }
        __syncthreads();
    }

    // ---- denominator reduce ----
#pragma unroll
    for (int r = 0; r < RW; ++r) {
        float v = den_acc[r];
#pragma unroll
        for (int o = 16; o; o >>= 1) v += __shfl_xor_sync(0xffffffffu, v, o);
        if (lane == 0) den_s[warp * RW + r] = v;
    }
    __syncthreads();

    // ---- epilogue ----
    int out_col0 = y * out_col_step;
    float* op = outp + (size_t)y * out_blk_step;
#pragma unroll
    for (int r = 0; r < R; ++r) {
        int i = i0 + r0 + r;
        float den = den_s[r0 + r];
        float vals[8];
#pragma unroll
        for (int k = 0; k < 4; ++k) unpack2(acc[r][k], vals[2 * k], vals[2 * k + 1]);
        if (FIN) {
            float inv = 1.0f / den;
#pragma unroll
            for (int k = 0; k < 8; ++k) {
                float v = vals[k] * inv;
                vals[k] = (v > 0.f) ? v : expm1f(v);   // ELU
            }
        }
        float4* p = (float4*)&op[(size_t)i * out_stride + out_col0 + c0];
        p[0] = make_float4(vals[0], vals[1], vals[2], vals[3]);
        p[1] = make_float4(vals[4], vals[5], vals[6], vals[7]);
        if (!FIN && ct == 0) den_out[(size_t)y * den_step + i] = den;
    }
}

// ---------------------------------------------------------------------------
// Combine layer-2 slice partials, normalize, ELU, write final output.
// ---------------------------------------------------------------------------
__global__ void combine2_kernel(float* __restrict__ out) {
    int idx = blockIdx.x * 256 + threadIdx.x;      // NN*ODIM = 524288
    int i = idx >> 7;
    float n = g_num2[idx] + g_num2[idx + NN * ODIM] +
              g_num2[idx + 2 * NN * ODIM] + g_num2[idx + 3 * NN * ODIM];
    float d = g_den2[i] + g_den2[i + NN] + g_den2[i + 2 * NN] + g_den2[i + 3 * NN];
    float v = n / d;
    out[idx] = (v > 0.f) ? v : expm1f(v);
}

// ---------------------------------------------------------------------------
// Host launch
// ---------------------------------------------------------------------------
extern "C" void kernel_launch(void* const* d_in, const int* in_sizes, int n_in,
                              void* d_out, int out_size) {
    const float* x       = (const float*)d_in[0];
    const int*   adj     = (const int*)  d_in[1];
    const float* W_heads = (const float*)d_in[2];
    const float* a_heads = (const float*)d_in[3];
    const float* W_out   = (const float*)d_in[4];
    const float* a_out   = (const float*)d_in[5];
    float* out = (float*)d_out;
    (void)in_sizes; (void)n_in; (void)out_size;

    void *pWcat, *pWh1, *pH1, *pWh2, *pF11, *pF21, *pF12, *pF22, *pNum2, *pDen2;
    cudaGetSymbolAddress(&pWcat, g_Wcat);
    cudaGetSymbolAddress(&pWh1,  g_Wh1);
    cudaGetSymbolAddress(&pH1,   g_h1);
    cudaGetSymbolAddress(&pWh2,  g_Wh2);
    cudaGetSymbolAddress(&pF11,  g_f11);
    cudaGetSymbolAddress(&pF21,  g_f21);
    cudaGetSymbolAddress(&pF12,  g_f12);
    cudaGetSymbolAddress(&pF22,  g_f22);
    cudaGetSymbolAddress(&pNum2, g_num2);
    cudaGetSymbolAddress(&pDen2, g_den2);

    constexpr int SMEM1 = 32 * 64  * 4 + 128 * 33 * 8 + 128 * 4;  // ~42.5 KB
    constexpr int SMEM2 = 32 * 128 * 4 + 128 * 33 * 8 + 128 * 4;  // ~50.7 KB
    cudaFuncSetAttribute(attn_kernel<64,  true>,
                         cudaFuncAttributeMaxDynamicSharedMemorySize, SMEM1);
    cudaFuncSetAttribute(attn_kernel<128, false>,
                         cudaFuncAttributeMaxDynamicSharedMemorySize, SMEM2);

    // ---- Layer 1 ----
    packw_kernel<<<256, 256>>>(W_heads);
    gemm_kernel<<<dim3(4, 64), 256>>>(x, (const float*)pWcat, (float*)pWh1,
                                      NN, 256, IN_DIM);
    fk1_kernel<<<NN / 8, 256>>>(a_heads);
    attn_kernel<64, true><<<dim3(32, NHEADS), 256, SMEM1>>>(
        (const float*)pWh1, 256, 64,
        (const float*)pF11, (const float*)pF21, NN,
        adj, 0, NN,
        (float*)pH1, 256, 64, 0,
        nullptr, 0);

    // ---- Layer 2 ----
    gemm_kernel<<<dim3(2, 64), 256>>>((const float*)pH1, W_out, (float*)pWh2,
                                      NN, ODIM, 256);
    fk2_kernel<<<NN / 8, 256>>>(a_out);
    attn_kernel<128, false><<<dim3(32, NSLICE), 256, SMEM2>>>(
        (const float*)pWh2, ODIM, 0,
        (const float*)pF12, (const float*)pF22, 0,
        adj, NN / NSLICE, NN / NSLICE,
        (float*)pNum2, ODIM, 0, NN * ODIM,
        (float*)pDen2, NN);

    combine2_kernel<<<NN * ODIM / 256, 256>>>(out);
}

// round 9
// speedup vs baseline: 1.2564x; 1.2564x over previous
#include <cuda_runtime.h>

// ---------------------------------------------------------------------------
// Problem constants
// ---------------------------------------------------------------------------
#define NN      4096
#define IN_DIM  256
#define HID     64
#define NHEADS  4
#define ODIM    128
#define NSL1    4          // j-split for layer-1 attention
#define NSL2    8          // j-split for layer-2 attention

// ---------------------------------------------------------------------------
// Scratch (device globals; no allocation allowed)
// ---------------------------------------------------------------------------
__device__ float    g_Wcat[IN_DIM * 256];
__device__ float    g_Wh1 [NN * 256];
__device__ float    g_f11 [NHEADS * NN];
__device__ float    g_f21 [NHEADS * NN];
__device__ float    g_h1  [NN * 256];
__device__ float    g_Wh2 [NN * ODIM];
__device__ float    g_f12 [NN];
__device__ float    g_f22 [NN];
__device__ float    g_num1[NSL1 * NN * 256];
__device__ float    g_den1[NSL1 * NHEADS * NN];
__device__ float    g_num2[NSL2 * NN * ODIM];
__device__ float    g_den2[NSL2 * NN];
__device__ unsigned g_bits[NN * (NN / 32)];     // adjacency bitmask, 2 MB

// ---------------------------------------------------------------------------
// Packed fp32x2 helpers (Blackwell)
// ---------------------------------------------------------------------------
__device__ __forceinline__ unsigned long long pack2(float v) {
    unsigned int u = __float_as_uint(v);
    unsigned long long r;
    asm("mov.b64 %0, {%1, %1};" : "=l"(r) : "r"(u));
    return r;
}
__device__ __forceinline__ void ffma2(unsigned long long &d,
                                      unsigned long long a,
                                      unsigned long long b) {
    asm("fma.rn.f32x2 %0, %1, %2, %0;" : "+l"(d) : "l"(a), "l"(b));
}
__device__ __forceinline__ void unpack2(unsigned long long v, float &lo, float &hi) {
    unsigned int a, b;
    asm("mov.b64 {%0, %1}, %2;" : "=r"(a), "=r"(b) : "l"(v));
    lo = __uint_as_float(a);
    hi = __uint_as_float(b);
}

// ---------------------------------------------------------------------------
// adj -> bitmask: one block per row, warp-ballot per 32-j word.
// ---------------------------------------------------------------------------
__global__ void bits_kernel(const int* __restrict__ adj) {
    int row  = blockIdx.x;
    int warp = threadIdx.x >> 5, lane = threadIdx.x & 31;
    for (int w = warp; w < NN / 32; w += 8) {
        unsigned m = __ballot_sync(0xffffffffu,
                                   adj[(size_t)row * NN + w * 32 + lane] != 0);
        if (lane == 0) g_bits[row * (NN / 32) + w] = m;
    }
}

// ---------------------------------------------------------------------------
// Pack W_heads [4][256][64] -> Wcat [256][256]
// ---------------------------------------------------------------------------
__global__ void packw_kernel(const float* __restrict__ W_heads) {
    int idx = blockIdx.x * 256 + threadIdx.x;
    int c = idx & 255;
    int h = c >> 6, f = c & 63;
    g_Wcat[idx] = W_heads[(h * 256 + (idx >> 8)) * 64 + f];
}

// ---------------------------------------------------------------------------
// Tiled fp32 GEMM: C[M,Nc] = A[M,K] @ B[K,Nc].  64x64 tile, BK=16.
// ---------------------------------------------------------------------------
__global__ __launch_bounds__(256)
void gemm_kernel(const float* __restrict__ A, const float* __restrict__ B,
                 float* __restrict__ C, int M, int Nc, int K) {
    __shared__ float As[16][65];
    __shared__ float Bs[16][64];
    int tid = threadIdx.x;
    int row0 = blockIdx.y * 64, col0 = blockIdx.x * 64;
    int tx = tid & 15, ty = tid >> 4;
    int am = tid >> 2, ak = (tid & 3) << 2;
    int bk = tid >> 4, bn = (tid & 15) << 2;
    float acc[4][4] = {};
    for (int k0 = 0; k0 < K; k0 += 16) {
        float4 av = *(const float4*)&A[(size_t)(row0 + am) * K + k0 + ak];
        As[ak + 0][am] = av.x; As[ak + 1][am] = av.y;
        As[ak + 2][am] = av.z; As[ak + 3][am] = av.w;
        *(float4*)&Bs[bk][bn] = *(const float4*)&B[(size_t)(k0 + bk) * Nc + col0 + bn];
        __syncthreads();
#pragma unroll
        for (int k = 0; k < 16; ++k) {
            float a[4];
#pragma unroll
            for (int r = 0; r < 4; ++r) a[r] = As[k][ty * 4 + r];
            float4 bv = *(const float4*)&Bs[k][tx * 4];
            float b[4] = {bv.x, bv.y, bv.z, bv.w};
#pragma unroll
            for (int r = 0; r < 4; ++r)
#pragma unroll
                for (int c = 0; c < 4; ++c)
                    acc[r][c] = fmaf(a[r], b[c], acc[r][c]);
        }
        __syncthreads();
    }
#pragma unroll
    for (int r = 0; r < 4; ++r)
#pragma unroll
        for (int c = 0; c < 4; ++c)
            C[(size_t)(row0 + ty * 4 + r) * Nc + col0 + tx * 4 + c] = acc[r][c];
}

// ---------------------------------------------------------------------------
// f-vectors
// ---------------------------------------------------------------------------
__global__ void fk1_kernel(const float* __restrict__ a_heads) {
    int warp = threadIdx.x >> 5, lane = threadIdx.x & 31;
    int i = blockIdx.x * 8 + warp;
#pragma unroll
    for (int h = 0; h < NHEADS; ++h) {
        float w0 = g_Wh1[(size_t)i * 256 + h * 64 + lane];
        float w1 = g_Wh1[(size_t)i * 256 + h * 64 + 32 + lane];
        float p1 = w0 * a_heads[h * 128 + lane]      + w1 * a_heads[h * 128 + 32 + lane];
        float p2 = w0 * a_heads[h * 128 + 64 + lane] + w1 * a_heads[h * 128 + 96 + lane];
#pragma unroll
        for (int o = 16; o; o >>= 1) {
            p1 += __shfl_xor_sync(0xffffffffu, p1, o);
            p2 += __shfl_xor_sync(0xffffffffu, p2, o);
        }
        if (lane == 0) { g_f11[h * NN + i] = p1; g_f21[h * NN + i] = p2; }
    }
}

__global__ void fk2_kernel(const float* __restrict__ a_out) {
    int warp = threadIdx.x >> 5, lane = threadIdx.x & 31;
    int i = blockIdx.x * 8 + warp;
    float s1 = 0.f, s2 = 0.f;
#pragma unroll
    for (int k = 0; k < 4; ++k) {
        float v = g_Wh2[(size_t)i * ODIM + k * 32 + lane];
        s1 = fmaf(v, a_out[k * 32 + lane], s1);
        s2 = fmaf(v, a_out[128 + k * 32 + lane], s2);
    }
#pragma unroll
    for (int o = 16; o; o >>= 1) {
        s1 += __shfl_xor_sync(0xffffffffu, s1, o);
        s2 += __shfl_xor_sync(0xffffffffu, s2, o);
    }
    if (lane == 0) { g_f12[i] = s1; g_f22[i] = s2; }
}

// ---------------------------------------------------------------------------
// Attention aggregation, slice-partial output.
//   blockIdx.x = i-block (BM=128 rows), .y = j-slice, .z = head.
//   Phase A: w tile from f1/f2 + bitmask (broadcast LDG, 1 word / 32 j).
//   Phase B: fp32x2 register-tiled MAC.
//   Output: raw numerator tile + per-row denominator (per slice/head).
// ---------------------------------------------------------------------------
template<int NF>
__global__ __launch_bounds__(256, 2)
void attn_kernel(const float* __restrict__ Wh, int wh_stride,
                 const float* __restrict__ f1b, const float* __restrict__ f2b,
                 int f_step,
                 int j_per_slice,
                 float* __restrict__ num_out, int num_stride, int out_col_step,
                 float* __restrict__ den_out) {
    constexpr int BM = 128, BN = 32;
    constexpr int Tc = NF / 8;
    constexpr int R  = BM / (256 / Tc);
    constexpr int RW = BM / 8;

    extern __shared__ unsigned char smraw[];
    unsigned long long* w_s = (unsigned long long*)smraw;        // [BM][BN+1]
    float* wh_s = (float*)(smraw + BM * (BN + 1) * 8);           // [BN][NF]

    int tid  = threadIdx.x, warp = tid >> 5, lane = tid & 31;
    int i0   = blockIdx.x * BM;
    int sl   = blockIdx.y, head = blockIdx.z;

    const float* f1 = f1b + head * f_step;
    const float* f2 = f2b + head * f_step;
    int wh_col0 = head * out_col_step;
    int j_begin = sl * j_per_slice, j_end = j_begin + j_per_slice;

    float f1r[RW], den_acc[RW];
#pragma unroll
    for (int r = 0; r < RW; ++r) {
        f1r[r] = f1[i0 + warp * RW + r];
        den_acc[r] = 0.f;
    }

    int ct = tid % Tc, rt = tid / Tc;
    int c0 = ct * 8, r0 = rt * R;
    unsigned long long acc[R][4];
#pragma unroll
    for (int r = 0; r < R; ++r)
#pragma unroll
        for (int k = 0; k < 4; ++k) acc[r][k] = 0ull;

    for (int j0 = j_begin; j0 < j_end; j0 += BN) {
        // ---- load Wh tile (coalesced float4) ----
#pragma unroll
        for (int t = 0; t < (BN * NF / 4) / 256; ++t) {
            int idx = t * 256 + tid;
            int jj = idx / (NF / 4), ff = (idx % (NF / 4)) * 4;
            *(float4*)&wh_s[jj * NF + ff] =
                *(const float4*)&Wh[(size_t)(j0 + jj) * wh_stride + wh_col0 + ff];
        }
        // ---- build w tile (bitmask word broadcast) ----
        float f2v = f2[j0 + lane];
        int word_col = j0 >> 5;
#pragma unroll
        for (int r = 0; r < RW; ++r) {
            int il = warp * RW + r;
            unsigned mw = g_bits[(i0 + il) * (NN / 32) + word_col];
            float s = f1r[r] + f2v;
            s = fmaxf(s, 0.5f * s);                 // leaky_relu, slope 0.5
            float w = ((mw >> lane) & 1u) ? __expf(s) : 0.0f;
            w_s[il * (BN + 1) + lane] = pack2(w);
            den_acc[r] += w;
        }
        __syncthreads();
        // ---- MAC phase ----
#pragma unroll 4
        for (int jj = 0; jj < BN; ++jj) {
            ulonglong2 wa = *(const ulonglong2*)&wh_s[jj * NF + c0];
            ulonglong2 wb = *(const ulonglong2*)&wh_s[jj * NF + c0 + 4];
#pragma unroll
            for (int r = 0; r < R; ++r) {
                unsigned long long w2 = w_s[(r0 + r) * (BN + 1) + jj];
                ffma2(acc[r][0], w2, wa.x);
                ffma2(acc[r][1], w2, wa.y);
                ffma2(acc[r][2], w2, wb.x);
                ffma2(acc[r][3], w2, wb.y);
            }
        }
        __syncthreads();
    }

    // ---- denominator reduce + store ----
    float* denp = den_out + (size_t)(sl * gridDim.z + head) * NN;
#pragma unroll
    for (int r = 0; r < RW; ++r) {
        float v = den_acc[r];
#pragma unroll
        for (int o = 16; o; o >>= 1) v += __shfl_xor_sync(0xffffffffu, v, o);
        if (lane == 0) denp[i0 + warp * RW + r] = v;
    }

    // ---- numerator store ----
    float* np = num_out + (size_t)sl * NN * num_stride;
#pragma unroll
    for (int r = 0; r < R; ++r) {
        int i = i0 + r0 + r;
        float vals[8];
#pragma unroll
        for (int k = 0; k < 4; ++k) unpack2(acc[r][k], vals[2 * k], vals[2 * k + 1]);
        float4* p = (float4*)&np[(size_t)i * num_stride + wh_col0 + c0];
        p[0] = make_float4(vals[0], vals[1], vals[2], vals[3]);
        p[1] = make_float4(vals[4], vals[5], vals[6], vals[7]);
    }
}

// ---------------------------------------------------------------------------
// Combine layer-1 partials: normalize + ELU -> g_h1
// ---------------------------------------------------------------------------
__global__ void combine1_kernel() {
    int idx = blockIdx.x * 256 + threadIdx.x;      // NN*256
    int i = idx >> 8, c = idx & 255, head = c >> 6;
    float n = 0.f, d = 0.f;
#pragma unroll
    for (int s = 0; s < NSL1; ++s) {
        n += g_num1[(size_t)s * NN * 256 + idx];
        d += g_den1[(s * NHEADS + head) * NN + i];
    }
    float v = n / d;
    g_h1[idx] = (v > 0.f) ? v : expm1f(v);
}

// ---------------------------------------------------------------------------
// Combine layer-2 partials: normalize + ELU -> out
// ---------------------------------------------------------------------------
__global__ void combine2_kernel(float* __restrict__ out) {
    int idx = blockIdx.x * 256 + threadIdx.x;      // NN*ODIM
    int i = idx >> 7;
    float n = 0.f, d = 0.f;
#pragma unroll
    for (int s = 0; s < NSL2; ++s) {
        n += g_num2[(size_t)s * NN * ODIM + idx];
        d += g_den2[s * NN + i];
    }
    float v = n / d;
    out[idx] = (v > 0.f) ? v : expm1f(v);
}

// ---------------------------------------------------------------------------
// Host launch
// ---------------------------------------------------------------------------
extern "C" void kernel_launch(void* const* d_in, const int* in_sizes, int n_in,
                              void* d_out, int out_size) {
    const float* x       = (const float*)d_in[0];
    const int*   adj     = (const int*)  d_in[1];
    const float* W_heads = (const float*)d_in[2];
    const float* a_heads = (const float*)d_in[3];
    const float* W_out   = (const float*)d_in[4];
    const float* a_out   = (const float*)d_in[5];
    float* out = (float*)d_out;
    (void)in_sizes; (void)n_in; (void)out_size;

    void *pWcat, *pWh1, *pH1, *pWh2, *pF11, *pF21, *pF12, *pF22;
    void *pNum1, *pDen1, *pNum2, *pDen2;
    cudaGetSymbolAddress(&pWcat, g_Wcat);
    cudaGetSymbolAddress(&pWh1,  g_Wh1);
    cudaGetSymbolAddress(&pH1,   g_h1);
    cudaGetSymbolAddress(&pWh2,  g_Wh2);
    cudaGetSymbolAddress(&pF11,  g_f11);
    cudaGetSymbolAddress(&pF21,  g_f21);
    cudaGetSymbolAddress(&pF12,  g_f12);
    cudaGetSymbolAddress(&pF22,  g_f22);
    cudaGetSymbolAddress(&pNum1, g_num1);
    cudaGetSymbolAddress(&pDen1, g_den1);
    cudaGetSymbolAddress(&pNum2, g_num2);
    cudaGetSymbolAddress(&pDen2, g_den2);

    constexpr int SMEM1 = 128 * 33 * 8 + 32 * 64  * 4;   // 41.0 KB
    constexpr int SMEM2 = 128 * 33 * 8 + 32 * 128 * 4;   // 49.0 KB
    cudaFuncSetAttribute(attn_kernel<64>,
                         cudaFuncAttributeMaxDynamicSharedMemorySize, SMEM1);
    cudaFuncSetAttribute(attn_kernel<128>,
                         cudaFuncAttributeMaxDynamicSharedMemorySize, SMEM2);

    // ---- prep ----
    bits_kernel<<<NN, 256>>>(adj);
    packw_kernel<<<256, 256>>>(W_heads);

    // ---- Layer 1 ----
    gemm_kernel<<<dim3(4, 64), 256>>>(x, (const float*)pWcat, (float*)pWh1,
                                      NN, 256, IN_DIM);
    fk1_kernel<<<NN / 8, 256>>>(a_heads);
    attn_kernel<64><<<dim3(32, NSL1, NHEADS), 256, SMEM1>>>(
        (const float*)pWh1, 256,
        (const float*)pF11, (const float*)pF21, NN,
        NN / NSL1,
        (float*)pNum1, 256, 64,
        (float*)pDen1);
    combine1_kernel<<<NN * 256 / 256, 256>>>();

    // ---- Layer 2 ----
    gemm_kernel<<<dim3(2, 64), 256>>>((const float*)pH1, W_out, (float*)pWh2,
                                      NN, ODIM, 256);
    fk2_kernel<<<NN / 8, 256>>>(a_out);
    attn_kernel<128><<<dim3(32, NSL2, 1), 256, SMEM2>>>(
        (const float*)pWh2, ODIM,
        (const float*)pF12, (const float*)pF22, 0,
        NN / NSL2,
        (float*)pNum2, ODIM, 0,
        (float*)pDen2);
    combine2_kernel<<<NN * ODIM / 256, 256>>>(out);
}

// round 12
// speedup vs baseline: 1.4374x; 1.1441x over previous
#include <cuda_runtime.h>

// ---------------------------------------------------------------------------
// Problem constants
// ---------------------------------------------------------------------------
#define NN      4096
#define IN_DIM  256
#define HID     64
#define NHEADS  4
#define ODIM    128
#define NSL1    4          // j-split for layer-1 attention
#define NSL2    8          // j-split for layer-2 attention

// ---------------------------------------------------------------------------
// Scratch (device globals; no allocation allowed)
// ---------------------------------------------------------------------------
__device__ float    g_Wcat[IN_DIM * 256];
__device__ float    g_Wh1 [NN * 256];
__device__ float    g_f11 [NHEADS * NN];
__device__ float    g_f21 [NHEADS * NN];
__device__ float    g_h1  [NN * 256];
__device__ float    g_Wh2 [NN * ODIM];
__device__ float    g_f12 [NN];
__device__ float    g_f22 [NN];
__device__ float    g_num1[NSL1 * NN * 256];
__device__ float    g_den1[NSL1 * NHEADS * NN];
__device__ float    g_num2[NSL2 * NN * ODIM];
__device__ float    g_den2[NSL2 * NN];
__device__ unsigned g_bits[NN * (NN / 32)];     // adjacency bitmask, 2 MB

// ---------------------------------------------------------------------------
// Packed fp32x2 + cp.async helpers (Blackwell)
// ---------------------------------------------------------------------------
__device__ __forceinline__ unsigned long long pack2(float v) {
    unsigned int u = __float_as_uint(v);
    unsigned long long r;
    asm("mov.b64 %0, {%1, %1};" : "=l"(r) : "r"(u));
    return r;
}
__device__ __forceinline__ void ffma2(unsigned long long &d,
                                      unsigned long long a,
                                      unsigned long long b) {
    asm("fma.rn.f32x2 %0, %1, %2, %0;" : "+l"(d) : "l"(a), "l"(b));
}
__device__ __forceinline__ void unpack2(unsigned long long v, float &lo, float &hi) {
    unsigned int a, b;
    asm("mov.b64 {%0, %1}, %2;" : "=r"(a), "=r"(b) : "l"(v));
    lo = __uint_as_float(a);
    hi = __uint_as_float(b);
}
__device__ __forceinline__ unsigned sptr(const void* p) {
    return (unsigned)__cvta_generic_to_shared(p);
}
__device__ __forceinline__ void cpa16(unsigned dst, const void* src) {
    asm volatile("cp.async.cg.shared.global [%0], [%1], 16;"
                 :: "r"(dst), "l"(src));
}
__device__ __forceinline__ void cpa4(unsigned dst, const void* src) {
    asm volatile("cp.async.ca.shared.global [%0], [%1], 4;"
                 :: "r"(dst), "l"(src));
}
#define CP_COMMIT() asm volatile("cp.async.commit_group;")
#define CP_WAIT1()  asm volatile("cp.async.wait_group 1;")

// ---------------------------------------------------------------------------
// adj -> bitmask: one block per row, warp-ballot per 32-j word.
// ---------------------------------------------------------------------------
__global__ void bits_kernel(const int* __restrict__ adj) {
    int row  = blockIdx.x;
    int warp = threadIdx.x >> 5, lane = threadIdx.x & 31;
    for (int w = warp; w < NN / 32; w += 8) {
        unsigned m = __ballot_sync(0xffffffffu,
                                   adj[(size_t)row * NN + w * 32 + lane] != 0);
        if (lane == 0) g_bits[row * (NN / 32) + w] = m;
    }
}

// ---------------------------------------------------------------------------
// Pack W_heads [4][256][64] -> Wcat [256][256]
// ---------------------------------------------------------------------------
__global__ void packw_kernel(const float* __restrict__ W_heads) {
    int idx = blockIdx.x * 256 + threadIdx.x;
    int c = idx & 255;
    int h = c >> 6, f = c & 63;
    g_Wcat[idx] = W_heads[(h * 256 + (idx >> 8)) * 64 + f];
}

// ---------------------------------------------------------------------------
// Tiled fp32 GEMM: C[M,Nc] = A[M,K] @ B[K,Nc].  64x64 tile, BK=16.
// ---------------------------------------------------------------------------
__global__ __launch_bounds__(256)
void gemm_kernel(const float* __restrict__ A, const float* __restrict__ B,
                 float* __restrict__ C, int M, int Nc, int K) {
    __shared__ float As[16][65];
    __shared__ float Bs[16][64];
    int tid = threadIdx.x;
    int row0 = blockIdx.y * 64, col0 = blockIdx.x * 64;
    int tx = tid & 15, ty = tid >> 4;
    int am = tid >> 2, ak = (tid & 3) << 2;
    int bk = tid >> 4, bn = (tid & 15) << 2;
    float acc[4][4] = {};
    for (int k0 = 0; k0 < K; k0 += 16) {
        float4 av = *(const float4*)&A[(size_t)(row0 + am) * K + k0 + ak];
        As[ak + 0][am] = av.x; As[ak + 1][am] = av.y;
        As[ak + 2][am] = av.z; As[ak + 3][am] = av.w;
        *(float4*)&Bs[bk][bn] = *(const float4*)&B[(size_t)(k0 + bk) * Nc + col0 + bn];
        __syncthreads();
#pragma unroll
        for (int k = 0; k < 16; ++k) {
            float a[4];
#pragma unroll
            for (int r = 0; r < 4; ++r) a[r] = As[k][ty * 4 + r];
            float4 bv = *(const float4*)&Bs[k][tx * 4];
            float b[4] = {bv.x, bv.y, bv.z, bv.w};
#pragma unroll
            for (int r = 0; r < 4; ++r)
#pragma unroll
                for (int c = 0; c < 4; ++c)
                    acc[r][c] = fmaf(a[r], b[c], acc[r][c]);
        }
        __syncthreads();
    }
#pragma unroll
    for (int r = 0; r < 4; ++r)
#pragma unroll
        for (int c = 0; c < 4; ++c)
            C[(size_t)(row0 + ty * 4 + r) * Nc + col0 + tx * 4 + c] = acc[r][c];
}

// ---------------------------------------------------------------------------
// f-vectors
// ---------------------------------------------------------------------------
__global__ void fk1_kernel(const float* __restrict__ a_heads) {
    int warp = threadIdx.x >> 5, lane = threadIdx.x & 31;
    int i = blockIdx.x * 8 + warp;
#pragma unroll
    for (int h = 0; h < NHEADS; ++h) {
        float w0 = g_Wh1[(size_t)i * 256 + h * 64 + lane];
        float w1 = g_Wh1[(size_t)i * 256 + h * 64 + 32 + lane];
        float p1 = w0 * a_heads[h * 128 + lane]      + w1 * a_heads[h * 128 + 32 + lane];
        float p2 = w0 * a_heads[h * 128 + 64 + lane] + w1 * a_heads[h * 128 + 96 + lane];
#pragma unroll
        for (int o = 16; o; o >>= 1) {
            p1 += __shfl_xor_sync(0xffffffffu, p1, o);
            p2 += __shfl_xor_sync(0xffffffffu, p2, o);
        }
        if (lane == 0) { g_f11[h * NN + i] = p1; g_f21[h * NN + i] = p2; }
    }
}

__global__ void fk2_kernel(const float* __restrict__ a_out) {
    int warp = threadIdx.x >> 5, lane = threadIdx.x & 31;
    int i = blockIdx.x * 8 + warp;
    float s1 = 0.f, s2 = 0.f;
#pragma unroll
    for (int k = 0; k < 4; ++k) {
        float v = g_Wh2[(size_t)i * ODIM + k * 32 + lane];
        s1 = fmaf(v, a_out[k * 32 + lane], s1);
        s2 = fmaf(v, a_out[128 + k * 32 + lane], s2);
    }
#pragma unroll
    for (int o = 16; o; o >>= 1) {
        s1 += __shfl_xor_sync(0xffffffffu, s1, o);
        s2 += __shfl_xor_sync(0xffffffffu, s2, o);
    }
    if (lane == 0) { g_f12[i] = s1; g_f22[i] = s2; }
}

// ---------------------------------------------------------------------------
// Attention aggregation, cp.async triple-buffered, conflict-free LDS.
//   blockIdx.x = i-block (BM=128 rows), .y = j-slice, .z = head.
//   Steady loop: phase A (w tile from smem-staged bits/f2), sync,
//   prefetch(t+2), MAC (fp32x2 register tile), sync at next top.
// ---------------------------------------------------------------------------
template<int NF>
__global__ __launch_bounds__(256, 2)
void attn_kernel(const float* __restrict__ Wh, int wh_stride,
                 const float* __restrict__ f1b, const float* __restrict__ f2b,
                 int f_step,
                 int j_per_slice,
                 float* __restrict__ num_out, int num_stride, int out_col_step,
                 float* __restrict__ den_out) {
    constexpr int BM = 128, BN = 32, WROW = 34;     // WROW even -> 16B-aligned jj pairs
    constexpr int Tc = NF / 8;
    constexpr int R  = BM / (256 / Tc);
    constexpr int RW = 16;

    extern __shared__ unsigned char smraw[];
    unsigned long long* w_s = (unsigned long long*)smraw;        // [BM][WROW]
    float*    wh_s   = (float*)(smraw + BM * WROW * 8);          // 3 x [BN][NF]
    unsigned* bits_s = (unsigned*)(wh_s + 3 * BN * NF);          // 3 x [BM]
    float*    f2_s   = (float*)(bits_s + 3 * BM);                // 3 x [BN]
    float*    f1_s   = f2_s + 3 * BN;                            // [BM]

    int tid  = threadIdx.x, warp = tid >> 5, lane = tid & 31;
    int i0   = blockIdx.x * BM;
    int sl   = blockIdx.y, head = blockIdx.z;

    const float* f1 = f1b + head * f_step;
    const float* f2 = f2b + head * f_step;
    int wh_col0 = head * out_col_step;
    int j_begin = sl * j_per_slice;
    int T = j_per_slice / BN;

    if (tid < BM) f1_s[tid] = f1[i0 + tid];

    int ct = tid % Tc, rt = tid / Tc;
    int c0 = ct * 4, r0 = rt * R;
    unsigned long long acc[R][4];
#pragma unroll
    for (int r = 0; r < R; ++r)
#pragma unroll
        for (int k = 0; k < 4; ++k) acc[r][k] = 0ull;
    float den_acc[RW];
#pragma unroll
    for (int r = 0; r < RW; ++r) den_acc[r] = 0.f;

    auto prefetch = [&](int tile, int buf) {
        int j0 = j_begin + tile * BN;
        float* whd = wh_s + buf * BN * NF;
#pragma unroll
        for (int t = 0; t < (BN * NF / 4) / 256; ++t) {
            int idx = t * 256 + tid;
            int jj = idx / (NF / 4), ff = (idx % (NF / 4)) * 4;
            cpa16(sptr(&whd[jj * NF + ff]),
                  &Wh[(size_t)(j0 + jj) * wh_stride + wh_col0 + ff]);
        }
        if (tid < BM)
            cpa4(sptr(&bits_s[buf * BM + tid]),
                 &g_bits[(size_t)(i0 + tid) * (NN / 32) + (j0 >> 5)]);
        else if (tid < BM + BN)
            cpa4(sptr(&f2_s[buf * BN + tid - BM]), &f2[j0 + tid - BM]);
    };

    prefetch(0, 0); CP_COMMIT();
    if (T > 1) prefetch(1, 1);
    CP_COMMIT();

    for (int t = 0; t < T; ++t) {
        int cur = t % 3;
        CP_WAIT1();
        __syncthreads();                       // buf cur ready; w_s free

        // ---- phase A: build w tile ----
        float f2v = f2_s[cur * BN + lane];
#pragma unroll
        for (int r = 0; r < RW; ++r) {
            int il = warp * RW + r;
            unsigned mw = bits_s[cur * BM + il];
            float s = f1_s[il] + f2v;
            s = fmaxf(s, 0.5f * s);            // leaky_relu, slope 0.5
            float w = ((mw >> lane) & 1u) ? __expf(s) : 0.0f;
            w_s[il * WROW + lane] = pack2(w);
            den_acc[r] += w;
        }
        __syncthreads();                       // w_s ready

        if (t + 2 < T) prefetch(t + 2, (t + 2) % 3);
        CP_COMMIT();

        // ---- MAC phase (paired jj, conflict-free wh chunks) ----
        const float* whc = wh_s + cur * BN * NF;
#pragma unroll 4
        for (int jp = 0; jp < BN; jp += 2) {
            ulonglong2 wa = *(const ulonglong2*)&whc[jp * NF + c0];
            ulonglong2 wb = *(const ulonglong2*)&whc[jp * NF + NF / 2 + c0];
            ulonglong2 va = *(const ulonglong2*)&whc[(jp + 1) * NF + c0];
            ulonglong2 vb = *(const ulonglong2*)&whc[(jp + 1) * NF + NF / 2 + c0];
#pragma unroll
            for (int r = 0; r < R; ++r) {
                ulonglong2 w2 = *(const ulonglong2*)&w_s[(r0 + r) * WROW + jp];
                ffma2(acc[r][0], w2.x, wa.x);
                ffma2(acc[r][1], w2.x, wa.y);
                ffma2(acc[r][2], w2.x, wb.x);
                ffma2(acc[r][3], w2.x, wb.y);
                ffma2(acc[r][0], w2.y, va.x);
                ffma2(acc[r][1], w2.y, va.y);
                ffma2(acc[r][2], w2.y, vb.x);
                ffma2(acc[r][3], w2.y, vb.y);
            }
        }
    }

    // ---- denominator reduce + store ----
    float* denp = den_out + (size_t)(sl * gridDim.z + head) * NN;
#pragma unroll
    for (int r = 0; r < RW; ++r) {
        float v = den_acc[r];
#pragma unroll
        for (int o = 16; o; o >>= 1) v += __shfl_xor_sync(0xffffffffu, v, o);
        if (lane == 0) denp[i0 + warp * RW + r] = v;
    }

    // ---- numerator store ----
    float* np = num_out + (size_t)sl * NN * num_stride;
#pragma unroll
    for (int r = 0; r < R; ++r) {
        int i = i0 + r0 + r;
        float v[8];
#pragma unroll
        for (int k = 0; k < 4; ++k) unpack2(acc[r][k], v[2 * k], v[2 * k + 1]);
        *(float4*)&np[(size_t)i * num_stride + wh_col0 + c0] =
            make_float4(v[0], v[1], v[2], v[3]);
        *(float4*)&np[(size_t)i * num_stride + wh_col0 + NF / 2 + c0] =
            make_float4(v[4], v[5], v[6], v[7]);
    }
}

// ---------------------------------------------------------------------------
// Combine layer-1 partials: normalize + ELU -> g_h1
// ---------------------------------------------------------------------------
__global__ void combine1_kernel() {
    int idx = blockIdx.x * 256 + threadIdx.x;      // NN*256
    int i = idx >> 8, c = idx & 255, head = c >> 6;
    float n = 0.f, d = 0.f;
#pragma unroll
    for (int s = 0; s < NSL1; ++s) {
        n += g_num1[(size_t)s * NN * 256 + idx];
        d += g_den1[(s * NHEADS + head) * NN + i];
    }
    float v = n / d;
    g_h1[idx] = (v > 0.f) ? v : expm1f(v);
}

// ---------------------------------------------------------------------------
// Combine layer-2 partials: normalize + ELU -> out
// ---------------------------------------------------------------------------
__global__ void combine2_kernel(float* __restrict__ out) {
    int idx = blockIdx.x * 256 + threadIdx.x;      // NN*ODIM
    int i = idx >> 7;
    float n = 0.f, d = 0.f;
#pragma unroll
    for (int s = 0; s < NSL2; ++s) {
        n += g_num2[(size_t)s * NN * ODIM + idx];
        d += g_den2[s * NN + i];
    }
    float v = n / d;
    out[idx] = (v > 0.f) ? v : expm1f(v);
}

// ---------------------------------------------------------------------------
// Host launch
// ---------------------------------------------------------------------------
extern "C" void kernel_launch(void* const* d_in, const int* in_sizes, int n_in,
                              void* d_out, int out_size) {
    const float* x       = (const float*)d_in[0];
    const int*   adj     = (const int*)  d_in[1];
    const float* W_heads = (const float*)d_in[2];
    const float* a_heads = (const float*)d_in[3];
    const float* W_out   = (const float*)d_in[4];
    const float* a_out   = (const float*)d_in[5];
    float* out = (float*)d_out;
    (void)in_sizes; (void)n_in; (void)out_size;

    void *pWcat, *pWh1, *pH1, *pWh2, *pF11, *pF21, *pF12, *pF22;
    void *pNum1, *pDen1, *pNum2, *pDen2;
    cudaGetSymbolAddress(&pWcat, g_Wcat);
    cudaGetSymbolAddress(&pWh1,  g_Wh1);
    cudaGetSymbolAddress(&pH1,   g_h1);
    cudaGetSymbolAddress(&pWh2,  g_Wh2);
    cudaGetSymbolAddress(&pF11,  g_f11);
    cudaGetSymbolAddress(&pF21,  g_f21);
    cudaGetSymbolAddress(&pF12,  g_f12);
    cudaGetSymbolAddress(&pF22,  g_f22);
    cudaGetSymbolAddress(&pNum1, g_num1);
    cudaGetSymbolAddress(&pDen1, g_den1);
    cudaGetSymbolAddress(&pNum2, g_num2);
    cudaGetSymbolAddress(&pDen2, g_den2);

    // smem: w_s + 3*wh + 3*bits + 3*f2 + f1
    constexpr int SMEM1 = 128 * 34 * 8 + 3 * 32 * 64  * 4 + 3 * 128 * 4
                        + 3 * 32 * 4 + 128 * 4;              // 61,824 B
    constexpr int SMEM2 = 128 * 34 * 8 + 3 * 32 * 128 * 4 + 3 * 128 * 4
                        + 3 * 32 * 4 + 128 * 4;              // 86,400 B
    cudaFuncSetAttribute(attn_kernel<64>,
                         cudaFuncAttributeMaxDynamicSharedMemorySize, SMEM1);
    cudaFuncSetAttribute(attn_kernel<128>,
                         cudaFuncAttributeMaxDynamicSharedMemorySize, SMEM2);

    // ---- prep ----
    bits_kernel<<<NN, 256>>>(adj);
    packw_kernel<<<256, 256>>>(W_heads);

    // ---- Layer 1 ----
    gemm_kernel<<<dim3(4, 64), 256>>>(x, (const float*)pWcat, (float*)pWh1,
                                      NN, 256, IN_DIM);
    fk1_kernel<<<NN / 8, 256>>>(a_heads);
    attn_kernel<64><<<dim3(32, NSL1, NHEADS), 256, SMEM1>>>(
        (const float*)pWh1, 256,
        (const float*)pF11, (const float*)pF21, NN,
        NN / NSL1,
        (float*)pNum1, 256, 64,
        (float*)pDen1);
    combine1_kernel<<<NN * 256 / 256, 256>>>();

    // ---- Layer 2 ----
    gemm_kernel<<<dim3(2, 64), 256>>>((const float*)pH1, W_out, (float*)pWh2,
                                      NN, ODIM, 256);
    fk2_kernel<<<NN / 8, 256>>>(a_out);
    attn_kernel<128><<<dim3(32, NSL2, 1), 256, SMEM2>>>(
        (const float*)pWh2, ODIM,
        (const float*)pF12, (const float*)pF22, 0,
        NN / NSL2,
        (float*)pNum2, ODIM, 0,
        (float*)pDen2);
    combine2_kernel<<<NN * ODIM / 256, 256>>>(out);
}

// round 14
// speedup vs baseline: 2.2492x; 1.5648x over previous
#include <cuda_runtime.h>
#include <cuda_bf16.h>

// ---------------------------------------------------------------------------
// Problem constants
// ---------------------------------------------------------------------------
#define NN      4096
#define IN_DIM  256
#define HID     64
#define NHEADS  4
#define ODIM    128
#define NSL1    4          // j-split for layer-1 attention
#define NSL2    8          // j-split for layer-2 attention

// ---------------------------------------------------------------------------
// Scratch (device globals; no allocation allowed)
// ---------------------------------------------------------------------------
__device__ float          g_Wcat[IN_DIM * 256];
__device__ float          g_Wh1 [NN * 256];
__device__ float          g_f11 [NHEADS * NN];
__device__ float          g_f21 [NHEADS * NN];
__device__ float          g_h1  [NN * 256];
__device__ float          g_Wh2 [NN * ODIM];
__device__ float          g_f12 [NN];
__device__ float          g_f22 [NN];
__device__ float          g_num1[NSL1 * NN * 256];
__device__ float          g_den1[NSL1 * NHEADS * NN];
__device__ float          g_num2[NSL2 * NN * ODIM];
__device__ float          g_den2[NSL2 * NN];
__device__ unsigned       g_bits[NN * (NN / 32)];   // adjacency bitmask, 2 MB
__device__ __nv_bfloat16  g_Wh1h[NN * 256];         // Wh1 hi (bf16)
__device__ __nv_bfloat16  g_Wh1l[NN * 256];         // Wh1 lo (bf16)
__device__ __nv_bfloat16  g_Wh2h[NN * ODIM];
__device__ __nv_bfloat16  g_Wh2l[NN * ODIM];

// ---------------------------------------------------------------------------
// PTX helpers: cp.async, ldmatrix, mma (bf16, m16n8k16, fp32 accum)
// ---------------------------------------------------------------------------
__device__ __forceinline__ unsigned sptr(const void* p) {
    return (unsigned)__cvta_generic_to_shared(p);
}
__device__ __forceinline__ void cpa16(unsigned dst, const void* src) {
    asm volatile("cp.async.cg.shared.global [%0], [%1], 16;"
                 :: "r"(dst), "l"(src));
}
__device__ __forceinline__ void cpa4(unsigned dst, const void* src) {
    asm volatile("cp.async.ca.shared.global [%0], [%1], 4;"
                 :: "r"(dst), "l"(src));
}
#define CP_COMMIT() asm volatile("cp.async.commit_group;")
#define CP_WAIT1()  asm volatile("cp.async.wait_group 1;")

__device__ __forceinline__ void ldsm4(unsigned* r, unsigned addr) {
    asm volatile("ldmatrix.sync.aligned.m8n8.x4.shared.b16 {%0,%1,%2,%3}, [%4];"
                 : "=r"(r[0]), "=r"(r[1]), "=r"(r[2]), "=r"(r[3]) : "r"(addr));
}
__device__ __forceinline__ void ldsm4t(unsigned* r, unsigned addr) {
    asm volatile("ldmatrix.sync.aligned.m8n8.x4.trans.shared.b16 {%0,%1,%2,%3}, [%4];"
                 : "=r"(r[0]), "=r"(r[1]), "=r"(r[2]), "=r"(r[3]) : "r"(addr));
}
__device__ __forceinline__ void mma16816(float* d, const unsigned* a,
                                         const unsigned* b) {
    asm volatile(
        "mma.sync.aligned.m16n8k16.row.col.f32.bf16.bf16.f32 "
        "{%0,%1,%2,%3}, {%4,%5,%6,%7}, {%8,%9}, {%0,%1,%2,%3};"
        : "+f"(d[0]), "+f"(d[1]), "+f"(d[2]), "+f"(d[3])
        : "r"(a[0]), "r"(a[1]), "r"(a[2]), "r"(a[3]), "r"(b[0]), "r"(b[1]));
}

// ---------------------------------------------------------------------------
// prep: adjacency bitmask (blocks 0..NN-1) + W_heads pack (blocks NN..NN+255)
// ---------------------------------------------------------------------------
__global__ void prep_kernel(const int* __restrict__ adj,
                            const float* __restrict__ W_heads) {
    if (blockIdx.x < NN) {
        int row  = blockIdx.x;
        int warp = threadIdx.x >> 5, lane = threadIdx.x & 31;
        for (int w = warp; w < NN / 32; w += 8) {
            unsigned m = __ballot_sync(0xffffffffu,
                                       adj[(size_t)row * NN + w * 32 + lane] != 0);
            if (lane == 0) g_bits[row * (NN / 32) + w] = m;
        }
    } else {
        int idx = (blockIdx.x - NN) * 256 + threadIdx.x;
        int c = idx & 255;
        int h = c >> 6, f = c & 63;
        g_Wcat[idx] = W_heads[(h * 256 + (idx >> 8)) * 64 + f];
    }
}

// ---------------------------------------------------------------------------
// Tiled fp32 GEMM: C[M,Nc] = A[M,K] @ B[K,Nc].  64x64 tile, BK=16.
// ---------------------------------------------------------------------------
__global__ __launch_bounds__(256)
void gemm_kernel(const float* __restrict__ A, const float* __restrict__ B,
                 float* __restrict__ C, int M, int Nc, int K) {
    __shared__ float As[16][65];
    __shared__ float Bs[16][64];
    int tid = threadIdx.x;
    int row0 = blockIdx.y * 64, col0 = blockIdx.x * 64;
    int tx = tid & 15, ty = tid >> 4;
    int am = tid >> 2, ak = (tid & 3) << 2;
    int bk = tid >> 4, bn = (tid & 15) << 2;
    float acc[4][4] = {};
    for (int k0 = 0; k0 < K; k0 += 16) {
        float4 av = *(const float4*)&A[(size_t)(row0 + am) * K + k0 + ak];
        As[ak + 0][am] = av.x; As[ak + 1][am] = av.y;
        As[ak + 2][am] = av.z; As[ak + 3][am] = av.w;
        *(float4*)&Bs[bk][bn] = *(const float4*)&B[(size_t)(k0 + bk) * Nc + col0 + bn];
        __syncthreads();
#pragma unroll
        for (int k = 0; k < 16; ++k) {
            float a[4];
#pragma unroll
            for (int r = 0; r < 4; ++r) a[r] = As[k][ty * 4 + r];
            float4 bv = *(const float4*)&Bs[k][tx * 4];
            float b[4] = {bv.x, bv.y, bv.z, bv.w};
#pragma unroll
            for (int r = 0; r < 4; ++r)
#pragma unroll
                for (int c = 0; c < 4; ++c)
                    acc[r][c] = fmaf(a[r], b[c], acc[r][c]);
        }
        __syncthreads();
    }
#pragma unroll
    for (int r = 0; r < 4; ++r)
#pragma unroll
        for (int c = 0; c < 4; ++c)
            C[(size_t)(row0 + ty * 4 + r) * Nc + col0 + tx * 4 + c] = acc[r][c];
}

// ---------------------------------------------------------------------------
// fsplit1: blocks [0,512) -> f1/f2 vectors (layer 1);
//          blocks [512, 512+4096) -> bf16 hi/lo split of Wh1.
// ---------------------------------------------------------------------------
__global__ void fsplit1_kernel(const float* __restrict__ a_heads) {
    if (blockIdx.x < 512) {
        int warp = threadIdx.x >> 5, lane = threadIdx.x & 31;
        int i = blockIdx.x * 8 + warp;
#pragma unroll
        for (int h = 0; h < NHEADS; ++h) {
            float w0 = g_Wh1[(size_t)i * 256 + h * 64 + lane];
            float w1 = g_Wh1[(size_t)i * 256 + h * 64 + 32 + lane];
            float p1 = w0 * a_heads[h * 128 + lane]      + w1 * a_heads[h * 128 + 32 + lane];
            float p2 = w0 * a_heads[h * 128 + 64 + lane] + w1 * a_heads[h * 128 + 96 + lane];
#pragma unroll
            for (int o = 16; o; o >>= 1) {
                p1 += __shfl_xor_sync(0xffffffffu, p1, o);
                p2 += __shfl_xor_sync(0xffffffffu, p2, o);
            }
            if (lane == 0) { g_f11[h * NN + i] = p1; g_f21[h * NN + i] = p2; }
        }
    } else {
        int idx = (blockIdx.x - 512) * 256 + threadIdx.x;   // NN*256
        float w = g_Wh1[idx];
        __nv_bfloat16 hi = __float2bfloat16(w);
        g_Wh1h[idx] = hi;
        g_Wh1l[idx] = __float2bfloat16(w - __bfloat162float(hi));
    }
}

// fsplit2: blocks [0,512) -> f vectors (layer 2); rest -> split Wh2.
__global__ void fsplit2_kernel(const float* __restrict__ a_out) {
    if (blockIdx.x < 512) {
        int warp = threadIdx.x >> 5, lane = threadIdx.x & 31;
        int i = blockIdx.x * 8 + warp;
        float s1 = 0.f, s2 = 0.f;
#pragma unroll
        for (int k = 0; k < 4; ++k) {
            float v = g_Wh2[(size_t)i * ODIM + k * 32 + lane];
            s1 = fmaf(v, a_out[k * 32 + lane], s1);
            s2 = fmaf(v, a_out[128 + k * 32 + lane], s2);
        }
#pragma unroll
        for (int o = 16; o; o >>= 1) {
            s1 += __shfl_xor_sync(0xffffffffu, s1, o);
            s2 += __shfl_xor_sync(0xffffffffu, s2, o);
        }
        if (lane == 0) { g_f12[i] = s1; g_f22[i] = s2; }
    } else {
        int idx = (blockIdx.x - 512) * 256 + threadIdx.x;   // NN*ODIM
        float w = g_Wh2[idx];
        __nv_bfloat16 hi = __float2bfloat16(w);
        g_Wh2h[idx] = hi;
        g_Wh2l[idx] = __float2bfloat16(w - __bfloat162float(hi));
    }
}

// ---------------------------------------------------------------------------
// Tensor-core attention aggregation (bf16 hi/lo split, 3-pass mma.sync).
//   blockIdx.x = i-block (128 rows), .y = j-slice, .z = head.
//   Per 32-j chunk: phase A builds w (fp32) -> bf16 hi/lo tiles in SMEM
//   (warp-private rows, ldmatrix-friendly pitch); MMA phase does
//   m16n8k16 bf16: acc += Ah*Bh + Al*Bh + Ah*Bl.  Wh tiles stream via
//   cp.async triple buffering.  Output: raw numerator + denominator.
// ---------------------------------------------------------------------------
template<int NF>
__global__ __launch_bounds__(256, 2)
void attn_kernel(const __nv_bfloat16* __restrict__ Whh,
                 const __nv_bfloat16* __restrict__ Whl, int wh_stride,
                 const float* __restrict__ f1b, const float* __restrict__ f2b,
                 int f_step, int j_per_slice,
                 float* __restrict__ num_out, int num_stride, int out_col_step,
                 float* __restrict__ den_out) {
    constexpr int BM = 128, BN = 32;
    constexpr int WP = 40;          // w tile pitch (bf16): 80 B, conflict-free
    constexpr int PW = NF + 8;      // Wh tile pitch (bf16), conflict-free
    constexpr int NT = NF / 8;      // n-tiles of 8 features

    extern __shared__ unsigned char smraw[];
    __nv_bfloat16* w_hi = (__nv_bfloat16*)smraw;                     // [128][WP]
    __nv_bfloat16* w_lo = w_hi + BM * WP;                            // [128][WP]
    __nv_bfloat16* wh_s = w_lo + BM * WP;          // 3 bufs x (hi [32][PW] + lo)
    unsigned* bits_s = (unsigned*)(wh_s + 3 * 2 * BN * PW);          // 3 x [128]
    float*    f2_s   = (float*)(bits_s + 3 * BM);                    // 3 x [32]
    float*    f1_s   = f2_s + 3 * BN;                                // [128]

    int tid  = threadIdx.x, warp = tid >> 5, lane = tid & 31;
    int i0   = blockIdx.x * BM;
    int sl   = blockIdx.y, head = blockIdx.z;

    const float* f1 = f1b + head * f_step;
    const float* f2 = f2b + head * f_step;
    int wh_col0 = head * out_col_step;
    int j_begin = sl * j_per_slice;
    int T = j_per_slice / BN;

    if (tid < BM) f1_s[tid] = f1[i0 + tid];

    float acc[NT][4];
#pragma unroll
    for (int n = 0; n < NT; ++n)
#pragma unroll
        for (int k = 0; k < 4; ++k) acc[n][k] = 0.f;
    float den_acc[16];
#pragma unroll
    for (int r = 0; r < 16; ++r) den_acc[r] = 0.f;

    auto prefetch = [&](int tile, int buf) {
        int j0 = j_begin + tile * BN;
        __nv_bfloat16* dh = wh_s + buf * (2 * BN * PW);
        __nv_bfloat16* dl = dh + BN * PW;
#pragma unroll
        for (int t = 0; t < NF / 64; ++t) {
            int idx = t * 256 + tid;
            int row = idx / (NF / 8), k8 = (idx % (NF / 8)) * 8;
            const size_t so = (size_t)(j0 + row) * wh_stride + wh_col0 + k8;
            cpa16(sptr(&dh[row * PW + k8]), &Whh[so]);
            cpa16(sptr(&dl[row * PW + k8]), &Whl[so]);
        }
        if (tid < BM)
            cpa4(sptr(&bits_s[buf * BM + tid]),
                 &g_bits[(size_t)(i0 + tid) * (NN / 32) + (j0 >> 5)]);
        else if (tid < BM + BN)
            cpa4(sptr(&f2_s[buf * BN + tid - BM]), &f2[j0 + tid - BM]);
    };

    prefetch(0, 0); CP_COMMIT();
    prefetch(1, 1); CP_COMMIT();

    for (int t = 0; t < T; ++t) {
        int cur = t % 3;
        CP_WAIT1();
        __syncthreads();               // buf cur ready; all warps past t-1 body

        // ---- phase A: build w hi/lo tiles (warp-private rows) ----
        float f2v = f2_s[cur * BN + lane];
#pragma unroll
        for (int r = 0; r < 16; ++r) {
            int il = warp * 16 + r;
            unsigned mw = bits_s[cur * BM + il];
            float s = f1_s[il] + f2v;
            s = fmaxf(s, 0.5f * s);    // leaky_relu, slope 0.5
            float w = ((mw >> lane) & 1u) ? __expf(s) : 0.0f;
            den_acc[r] += w;
            __nv_bfloat16 hi = __float2bfloat16(w);
            w_hi[il * WP + lane] = hi;
            w_lo[il * WP + lane] = __float2bfloat16(w - __bfloat162float(hi));
        }

        if (t + 2 < T) prefetch(t + 2, (t + 2) % 3);
        CP_COMMIT();

        // ---- MMA phase ----
        const __nv_bfloat16* whh = wh_s + cur * (2 * BN * PW);
        const __nv_bfloat16* whl = whh + BN * PW;
        int arow = warp * 16 + (lane & 15);
        int asub = (lane >> 4) * 8;
#pragma unroll
        for (int ks = 0; ks < 2; ++ks) {
            unsigned ah[4], al[4];
            ldsm4(ah, sptr(&w_hi[arow * WP + ks * 16 + asub]));
            ldsm4(al, sptr(&w_lo[arow * WP + ks * 16 + asub]));
            int brow = ks * 16 + (lane & 15);
#pragma unroll
            for (int fg = 0; fg < NF / 16; ++fg) {
                unsigned bh[4], bl[4];
                ldsm4t(bh, sptr(&whh[brow * PW + fg * 16 + asub]));
                ldsm4t(bl, sptr(&whl[brow * PW + fg * 16 + asub]));
                mma16816(acc[2 * fg],     ah, bh + 0);
                mma16816(acc[2 * fg],     al, bh + 0);
                mma16816(acc[2 * fg],     ah, bl + 0);
                mma16816(acc[2 * fg + 1], ah, bh + 2);
                mma16816(acc[2 * fg + 1], al, bh + 2);
                mma16816(acc[2 * fg + 1], ah, bl + 2);
            }
        }
    }

    // ---- denominator reduce + store ----
    float* denp = den_out + (size_t)(sl * gridDim.z + head) * NN;
#pragma unroll
    for (int r = 0; r < 16; ++r) {
        float v = den_acc[r];
#pragma unroll
        for (int o = 16; o; o >>= 1) v += __shfl_xor_sync(0xffffffffu, v, o);
        if (lane == 0) denp[i0 + warp * 16 + r] = v;
    }

    // ---- numerator store (mma D fragment layout) ----
    float* np = num_out + (size_t)sl * NN * num_stride;
    int g = lane >> 2, tt = lane & 3;
    int ra = i0 + warp * 16 + g;
#pragma unroll
    for (int nt = 0; nt < NT; ++nt) {
        int col = wh_col0 + nt * 8 + 2 * tt;
        *(float2*)&np[(size_t)ra * num_stride + col] =
            make_float2(acc[nt][0], acc[nt][1]);
        *(float2*)&np[(size_t)(ra + 8) * num_stride + col] =
            make_float2(acc[nt][2], acc[nt][3]);
    }
}

// ---------------------------------------------------------------------------
// Combine layer-1 partials: normalize + ELU -> g_h1
// ---------------------------------------------------------------------------
__global__ void combine1_kernel() {
    int idx = blockIdx.x * 256 + threadIdx.x;      // NN*256
    int i = idx >> 8, c = idx & 255, head = c >> 6;
    float n = 0.f, d = 0.f;
#pragma unroll
    for (int s = 0; s < NSL1; ++s) {
        n += g_num1[(size_t)s * NN * 256 + idx];
        d += g_den1[(s * NHEADS + head) * NN + i];
    }
    float v = n / d;
    g_h1[idx] = (v > 0.f) ? v : expm1f(v);
}

// ---------------------------------------------------------------------------
// Combine layer-2 partials: normalize + ELU -> out
// ---------------------------------------------------------------------------
__global__ void combine2_kernel(float* __restrict__ out) {
    int idx = blockIdx.x * 256 + threadIdx.x;      // NN*ODIM
    int i = idx >> 7;
    float n = 0.f, d = 0.f;
#pragma unroll
    for (int s = 0; s < NSL2; ++s) {
        n += g_num2[(size_t)s * NN * ODIM + idx];
        d += g_den2[s * NN + i];
    }
    float v = n / d;
    out[idx] = (v > 0.f) ? v : expm1f(v);
}

// ---------------------------------------------------------------------------
// Host launch
// ---------------------------------------------------------------------------
extern "C" void kernel_launch(void* const* d_in, const int* in_sizes, int n_in,
                              void* d_out, int out_size) {
    const float* x       = (const float*)d_in[0];
    const int*   adj     = (const int*)  d_in[1];
    const float* W_heads = (const float*)d_in[2];
    const float* a_heads = (const float*)d_in[3];
    const float* W_out   = (const float*)d_in[4];
    const float* a_out   = (const float*)d_in[5];
    float* out = (float*)d_out;
    (void)in_sizes; (void)n_in; (void)out_size;

    void *pWcat, *pWh1, *pH1, *pWh2, *pF11, *pF21, *pF12, *pF22;
    void *pNum1, *pDen1, *pNum2, *pDen2, *pW1h, *pW1l, *pW2h, *pW2l;
    cudaGetSymbolAddress(&pWcat, g_Wcat);
    cudaGetSymbolAddress(&pWh1,  g_Wh1);
    cudaGetSymbolAddress(&pH1,   g_h1);
    cudaGetSymbolAddress(&pWh2,  g_Wh2);
    cudaGetSymbolAddress(&pF11,  g_f11);
    cudaGetSymbolAddress(&pF21,  g_f21);
    cudaGetSymbolAddress(&pF12,  g_f12);
    cudaGetSymbolAddress(&pF22,  g_f22);
    cudaGetSymbolAddress(&pNum1, g_num1);
    cudaGetSymbolAddress(&pDen1, g_den1);
    cudaGetSymbolAddress(&pNum2, g_num2);
    cudaGetSymbolAddress(&pDen2, g_den2);
    cudaGetSymbolAddress(&pW1h,  g_Wh1h);
    cudaGetSymbolAddress(&pW1l,  g_Wh1l);
    cudaGetSymbolAddress(&pW2h,  g_Wh2h);
    cudaGetSymbolAddress(&pW2l,  g_Wh2l);

    // smem: w_hi + w_lo + 3*2*wh + bits + f2 + f1
    constexpr int SMEM1 = 2 * 128 * 40 * 2 + 3 * 2 * 32 * 72  * 2
                        + 3 * 128 * 4 + 3 * 32 * 4 + 128 * 4;   // 50,560 B
    constexpr int SMEM2 = 2 * 128 * 40 * 2 + 3 * 2 * 32 * 136 * 2
                        + 3 * 128 * 4 + 3 * 32 * 4 + 128 * 4;   // 75,136 B
    cudaFuncSetAttribute(attn_kernel<64>,
                         cudaFuncAttributeMaxDynamicSharedMemorySize, SMEM1);
    cudaFuncSetAttribute(attn_kernel<128>,
                         cudaFuncAttributeMaxDynamicSharedMemorySize, SMEM2);

    // ---- prep (launch 1) ----
    prep_kernel<<<NN + 256, 256>>>(adj, W_heads);

    // ---- Layer 1 ----
    gemm_kernel<<<dim3(4, 64), 256>>>(x, (const float*)pWcat, (float*)pWh1,
                                      NN, 256, IN_DIM);                 // 2
    fsplit1_kernel<<<512 + 4096, 256>>>(a_heads);                       // 3
    attn_kernel<64><<<dim3(32, NSL1, NHEADS), 256, SMEM1>>>(            // 4 (profiled)
        (const __nv_bfloat16*)pW1h, (const __nv_bfloat16*)pW1l, 256,
        (const float*)pF11, (const float*)pF21, NN,
        NN / NSL1,
        (float*)pNum1, 256, 64,
        (float*)pDen1);
    combine1_kernel<<<NN * 256 / 256, 256>>>();                         // 5

    // ---- Layer 2 ----
    gemm_kernel<<<dim3(2, 64), 256>>>((const float*)pH1, W_out, (float*)pWh2,
                                      NN, ODIM, 256);                   // 6
    fsplit2_kernel<<<512 + 2048, 256>>>(a_out);                         // 7
    attn_kernel<128><<<dim3(32, NSL2, 1), 256, SMEM2>>>(                // 8
        (const __nv_bfloat16*)pW2h, (const __nv_bfloat16*)pW2l, ODIM,
        (const float*)pF12, (const float*)pF22, 0,
        NN / NSL2,
        (float*)pNum2, ODIM, 0,
        (float*)pDen2);
    combine2_kernel<<<NN * ODIM / 256, 256>>>(out);                     // 9
}